// round 5
// baseline (speedup 1.0000x reference)
#include <cuda_runtime.h>
#include <cuda_bf16.h>
#include <mma.h>
#include <cstdint>
#include <cstddef>

using namespace nvcuda;

#define CC 256
#define PP 4096
#define NN 262144

// ---------------- scratch (device globals: no allocation allowed) ----------------
static __device__ float g_G   [PP * CC];   // LN(segment mean of dg)
static __device__ float g_ATT [PP * CC];   // attn (= residual)
static __device__ float g_Y   [PP * CC];   // LN(attn)
static __device__ float g_H   [PP * CC];   // relu(y@W1.T+b1)
static __device__ float g_DG  [PP * CC];   // dg
static __device__ float g_G2  [PP * CC];   // dg@Wf2.T + fuse_b
static __device__ float g_WVO [CC * CC];   // out_proj_w @ Wv
static __device__ float g_BVO [CC];        // out_proj_w @ bv + bo
static __device__ float g_WF  [CC * CC];   // W'[n,k] = node_w[k]*fuse_w1[n,k]
static __device__ float g_U   [CC];        // u[n] = sum_k W'[n,k]
static __device__ float g_V   [CC];        // v[n] = sum_k node_b[k]*fuse_w1[n,k]
static __device__ float g_MU  [NN];        // per-row mean of orig
static __device__ float g_RS  [NN];        // per-row rstd of orig

// ---------------- cp.async helpers ----------------
__device__ __forceinline__ void cp_async16(void* smem, const void* gmem) {
    uint32_t s = (uint32_t)__cvta_generic_to_shared(smem);
    asm volatile("cp.async.cg.shared.global [%0], [%1], 16;\n" :: "r"(s), "l"(gmem));
}
#define CP_COMMIT() asm volatile("cp.async.commit_group;\n" ::: "memory")
#define CP_WAIT(n)  asm volatile("cp.async.wait_group %0;\n" :: "n"(n) : "memory")

// ---------------- fold Wvo = Wo @ Wv, bvo = Wo @ bv + bo ----------------
__global__ void make_wvo(const float* __restrict__ Wo, const float* __restrict__ Wv,
                         const float* __restrict__ bv, const float* __restrict__ bo,
                         float* __restrict__ Wvo, float* __restrict__ bvo)
{
    const int i = blockIdx.x;
    const int t = threadIdx.x;
    __shared__ float sWo[CC];
    __shared__ float red[CC];
    sWo[t] = Wo[i * CC + t];
    __syncthreads();
    float s = 0.f;
    #pragma unroll 8
    for (int j = 0; j < CC; j++) s += sWo[j] * Wv[j * CC + t];
    Wvo[i * CC + t] = s;
    red[t] = sWo[t] * bv[t];
    __syncthreads();
    for (int o = 128; o > 0; o >>= 1) {
        if (t < o) red[t] += red[t + o];
        __syncthreads();
    }
    if (t == 0) bvo[i] = red[0] + bo[i];
}

// ---------------- W' = node_w ∘ fuse_w1 ; u = rowsum(W'); v = node_b @ fuse_w1.T ----------------
__global__ void prep_fuse(const float* __restrict__ fuse_w, const float* __restrict__ nw,
                          const float* __restrict__ nb,
                          float* __restrict__ Wp, float* __restrict__ u, float* __restrict__ v)
{
    const int n = blockIdx.x;
    const int k = threadIdx.x;
    __shared__ float r1[CC], r2[CC];
    const float fw = fuse_w[(size_t)n * 2 * CC + k];   // first-half column k
    const float wv = nw[k] * fw;
    Wp[n * CC + k] = wv;
    r1[k] = wv;
    r2[k] = nb[k] * fw;
    __syncthreads();
    for (int o = 128; o > 0; o >>= 1) {
        if (k < o) { r1[k] += r1[k + o]; r2[k] += r2[k + o]; }
        __syncthreads();
    }
    if (k == 0) { u[n] = r1[0]; v[n] = r2[0]; }
}

// ---------------- per-row LN statistics of orig (warp per row) ----------------
__global__ void ln_stats(const float4* __restrict__ in, float* __restrict__ mu,
                         float* __restrict__ rs, int rows)
{
    const int warp = blockIdx.x * 8 + (threadIdx.x >> 5);
    if (warp >= rows) return;
    const int lane = threadIdx.x & 31;
    const float4* rp = in + (size_t)warp * 64;
    float4 a = rp[lane], b = rp[lane + 32];
    float s  = a.x + a.y + a.z + a.w + b.x + b.y + b.z + b.w;
    float s2 = a.x*a.x + a.y*a.y + a.z*a.z + a.w*a.w
             + b.x*b.x + b.y*b.y + b.z*b.z + b.w*b.w;
    #pragma unroll
    for (int o = 16; o > 0; o >>= 1) {
        s  += __shfl_xor_sync(0xFFFFFFFFu, s,  o);
        s2 += __shfl_xor_sync(0xFFFFFFFFu, s2, o);
    }
    if (lane == 0) {
        const float m = s * (1.f / CC);
        const float var = s2 * (1.f / CC) - m * m;
        mu[warp] = m;
        rs[warp] = rsqrtf(var + 1e-5f);
    }
}

// ---------------- segment mean (sorted batch) fused with dg LayerNorm ----------------
__global__ void seg_mean_ln(const float* __restrict__ dg, const int* __restrict__ batch, int n,
                            const float* __restrict__ w, const float* __restrict__ b,
                            float* __restrict__ gout)
{
    const int p = blockIdx.x;
    const int t = threadIdx.x;
    __shared__ int sb[2];
    __shared__ float red[CC];
    if (t < 2) {
        int target = p + t;
        int lo = 0, hi = n;
        while (lo < hi) {
            int mid = (lo + hi) >> 1;
            if (batch[mid] < target) lo = mid + 1; else hi = mid;
        }
        sb[t] = lo;
    }
    __syncthreads();
    const int start = sb[0], end = sb[1];
    float s = 0.f;
    for (int r = start; r < end; r++) s += dg[(size_t)r * CC + t];
    const int cnt = end - start;
    float mv = (cnt > 0) ? s / (float)cnt : 0.f;

    red[t] = mv; __syncthreads();
    for (int o = 128; o > 0; o >>= 1) { if (t < o) red[t] += red[t + o]; __syncthreads(); }
    const float mu = red[0] * (1.f / CC);
    __syncthreads();
    red[t] = mv * mv; __syncthreads();
    for (int o = 128; o > 0; o >>= 1) { if (t < o) red[t] += red[t + o]; __syncthreads(); }
    const float var = red[0] * (1.f / CC) - mu * mu;
    const float rstd = rsqrtf(var + 1e-5f);
    gout[(size_t)p * CC + t] = (mv - mu) * rstd * w[t] + b[t];
}

// ---------------- warp-per-row LayerNorm (P rows only) ----------------
__global__ void ln_rows(const float* __restrict__ in, const float* __restrict__ w,
                        const float* __restrict__ b, float* __restrict__ out, int rows)
{
    const int warp = blockIdx.x * (blockDim.x >> 5) + (threadIdx.x >> 5);
    if (warp >= rows) return;
    const int lane = threadIdx.x & 31;
    const float* rp = in + (size_t)warp * CC;
    float v[8];
    float s = 0.f, s2 = 0.f;
    #pragma unroll
    for (int i = 0; i < 8; i++) {
        v[i] = rp[lane + 32 * i];
        s  += v[i];
        s2 += v[i] * v[i];
    }
    #pragma unroll
    for (int o = 16; o > 0; o >>= 1) {
        s  += __shfl_xor_sync(0xFFFFFFFFu, s,  o);
        s2 += __shfl_xor_sync(0xFFFFFFFFu, s2, o);
    }
    const float mu  = s * (1.f / CC);
    const float var = s2 * (1.f / CC) - mu * mu;
    const float rstd = rsqrtf(var + 1e-5f);
    float* op = out + (size_t)warp * CC;
    #pragma unroll
    for (int i = 0; i < 8; i++) {
        const int c = lane + 32 * i;
        op[c] = (v[i] - mu) * rstd * w[c] + b[c];
    }
}

// ---------------- small tf32 GEMM (P-row chain): C = A @ B.T + epilogue ----------------
constexpr int BM = 128, BN = 64, BK = 32;
constexpr int LA = BK + 4;
constexpr int LC = BN + 4;

template<bool RELU>
__global__ __launch_bounds__(256)
void gemm_small(const float* __restrict__ A,
                const float* __restrict__ B, int ldb,
                float* __restrict__ C,
                const float* __restrict__ bias,
                const float* __restrict__ res)
{
    __shared__ __align__(16) float smem[BM * LC];
    float* As = smem;
    float* Bs = smem + BM * LA;

    const int tid = threadIdx.x;
    const int warpId = tid >> 5;
    const int wm = warpId & 3;
    const int wn = warpId >> 2;
    const size_t gm = (size_t)blockIdx.y * BM;
    const int gn = blockIdx.x * BN;

    wmma::fragment<wmma::accumulator, 16, 16, 8, float> acc[2][2];
    #pragma unroll
    for (int i = 0; i < 2; i++)
        #pragma unroll
        for (int j = 0; j < 2; j++)
            wmma::fill_fragment(acc[i][j], 0.0f);

    const int lr = tid >> 3;
    const int lc = (tid & 7) << 2;

    for (int k0 = 0; k0 < CC; k0 += BK) {
        __syncthreads();
        #pragma unroll
        for (int p = 0; p < 4; p++) {
            const int r = lr + 32 * p;
            float4 v = *reinterpret_cast<const float4*>(A + (gm + r) * CC + k0 + lc);
            v.x = wmma::__float_to_tf32(v.x); v.y = wmma::__float_to_tf32(v.y);
            v.z = wmma::__float_to_tf32(v.z); v.w = wmma::__float_to_tf32(v.w);
            *reinterpret_cast<float4*>(&As[r * LA + lc]) = v;
        }
        #pragma unroll
        for (int p = 0; p < 2; p++) {
            const int r = lr + 32 * p;
            float4 v = *reinterpret_cast<const float4*>(B + (size_t)(gn + r) * ldb + k0 + lc);
            v.x = wmma::__float_to_tf32(v.x); v.y = wmma::__float_to_tf32(v.y);
            v.z = wmma::__float_to_tf32(v.z); v.w = wmma::__float_to_tf32(v.w);
            *reinterpret_cast<float4*>(&Bs[r * LA + lc]) = v;
        }
        __syncthreads();
        #pragma unroll
        for (int kk = 0; kk < BK; kk += 8) {
            wmma::fragment<wmma::matrix_a, 16, 16, 8, wmma::precision::tf32, wmma::row_major> af[2];
            wmma::fragment<wmma::matrix_b, 16, 16, 8, wmma::precision::tf32, wmma::col_major> bf[2];
            #pragma unroll
            for (int i = 0; i < 2; i++)
                wmma::load_matrix_sync(af[i], &As[(wm * 32 + 16 * i) * LA + kk], LA);
            #pragma unroll
            for (int j = 0; j < 2; j++)
                wmma::load_matrix_sync(bf[j], &Bs[(wn * 32 + 16 * j) * LA + kk], LA);
            #pragma unroll
            for (int i = 0; i < 2; i++)
                #pragma unroll
                for (int j = 0; j < 2; j++)
                    wmma::mma_sync(acc[i][j], af[i], bf[j], acc[i][j]);
        }
    }
    __syncthreads();
    #pragma unroll
    for (int i = 0; i < 2; i++)
        #pragma unroll
        for (int j = 0; j < 2; j++)
            wmma::store_matrix_sync(&smem[(wm * 32 + 16 * i) * LC + wn * 32 + 16 * j],
                                    acc[i][j], LC, wmma::mem_row_major);
    __syncthreads();

    const int ec = tid & 63;
    const int er = tid >> 6;
    #pragma unroll 4
    for (int r = er; r < BM; r += 4) {
        float c = smem[r * LC + ec];
        const size_t row = gm + r;
        const int col = gn + ec;
        if (bias) c += bias[col];
        if (res)  c += res[row * CC + col];
        if (RELU) c = fmaxf(c, 0.0f);
        C[row * CC + col] = c;
    }
}

// ---------------- BIG pipelined tf32 GEMM over raw orig, LN folded into epilogue ----------------
// out[row,col] = relu( rstd_r*(orig@W'.T) - rstd_r*mu_r*u[col] + v[col] + g2[batch[row],col] )
//               + (orig[row,col]-mu_r)*rstd_r*nw[col] + nb[col]
constexpr int GBM = 128, GBN = 128, GBK = 32;
constexpr int GLA = 36;
constexpr int SSTRIDE = (GBM + GBN) * GLA;   // 9216 floats per stage
constexpr int EPILD = GBN + 4;               // 132
constexpr int DSMEM_BYTES = 2 * SSTRIDE * 4 > GBM * EPILD * 4
                          ? 2 * SSTRIDE * 4 : GBM * EPILD * 4;  // 73728

__global__ __launch_bounds__(256, 2)
void gemm_big(const float* __restrict__ A,     // orig [N,256]
              const float* __restrict__ Bw,    // W'  [256,256]
              const float* __restrict__ mu_, const float* __restrict__ rs_,
              const float* __restrict__ uvec, const float* __restrict__ vvec,
              const int*   __restrict__ batch, const float* __restrict__ g2,
              const float* __restrict__ nw, const float* __restrict__ nb,
              float* __restrict__ out)
{
    extern __shared__ __align__(16) float dsm[];
    const int tid = threadIdx.x;
    const int warpId = tid >> 5;
    const int wm = warpId & 3;      // 4 row groups × 32 rows
    const int wn = warpId >> 2;     // 2 col groups × 64 cols
    const size_t gm = (size_t)blockIdx.y * GBM;
    const int gn = blockIdx.x * GBN;

    wmma::fragment<wmma::accumulator, 16, 16, 8, float> acc[2][4];
    #pragma unroll
    for (int i = 0; i < 2; i++)
        #pragma unroll
        for (int j = 0; j < 4; j++)
            wmma::fill_fragment(acc[i][j], 0.0f);

    auto load_stage = [&](int s, int k0) {
        float* As = dsm + s * SSTRIDE;
        float* Bs = As + GBM * GLA;
        #pragma unroll
        for (int p = 0; p < 4; p++) {
            const int idx = p * 256 + tid;
            const int r = idx >> 3, c = (idx & 7) << 2;
            cp_async16(&As[r * GLA + c], A + (gm + r) * CC + k0 + c);
        }
        #pragma unroll
        for (int p = 0; p < 4; p++) {
            const int idx = p * 256 + tid;
            const int r = idx >> 3, c = (idx & 7) << 2;
            cp_async16(&Bs[r * GLA + c], Bw + (size_t)(gn + r) * CC + k0 + c);
        }
    };

    load_stage(0, 0);
    CP_COMMIT();

    #pragma unroll 1
    for (int kt = 0; kt < CC / GBK; kt++) {
        if (kt + 1 < CC / GBK) {
            load_stage((kt + 1) & 1, (kt + 1) * GBK);
            CP_COMMIT();
            CP_WAIT(1);
        } else {
            CP_WAIT(0);
        }
        __syncthreads();

        float* As = dsm + (kt & 1) * SSTRIDE;
        float* Bs = As + GBM * GLA;
        #pragma unroll
        for (int kk = 0; kk < GBK; kk += 8) {
            wmma::fragment<wmma::matrix_a, 16, 16, 8, wmma::precision::tf32, wmma::row_major> af[2];
            wmma::fragment<wmma::matrix_b, 16, 16, 8, wmma::precision::tf32, wmma::col_major> bf[4];
            #pragma unroll
            for (int i = 0; i < 2; i++) {
                wmma::load_matrix_sync(af[i], &As[(wm * 32 + 16 * i) * GLA + kk], GLA);
                #pragma unroll
                for (int e = 0; e < af[i].num_elements; e++)
                    af[i].x[e] = wmma::__float_to_tf32(af[i].x[e]);
            }
            #pragma unroll
            for (int j = 0; j < 4; j++) {
                wmma::load_matrix_sync(bf[j], &Bs[(wn * 64 + 16 * j) * GLA + kk], GLA);
                #pragma unroll
                for (int e = 0; e < bf[j].num_elements; e++)
                    bf[j].x[e] = wmma::__float_to_tf32(bf[j].x[e]);
            }
            #pragma unroll
            for (int i = 0; i < 2; i++)
                #pragma unroll
                for (int j = 0; j < 4; j++)
                    wmma::mma_sync(acc[i][j], af[i], bf[j], acc[i][j]);
        }
        __syncthreads();
    }

    // epilogue: acc -> smem -> fused LN/residual/relu/gather -> out
    #pragma unroll
    for (int i = 0; i < 2; i++)
        #pragma unroll
        for (int j = 0; j < 4; j++)
            wmma::store_matrix_sync(&dsm[(wm * 32 + 16 * i) * EPILD + wn * 64 + 16 * j],
                                    acc[i][j], EPILD, wmma::mem_row_major);
    __syncthreads();

    const int ec = tid & 127;
    const int col = gn + ec;
    const float un = uvec[col], vn = vvec[col];
    const float w_ = nw[col],  b_ = nb[col];
    #pragma unroll 4
    for (int r = tid >> 7; r < GBM; r += 2) {
        const size_t row = gm + r;
        const float mu = mu_[row], rs = rs_[row];
        float c = dsm[r * EPILD + ec] * rs - mu * rs * un + vn
                + g2[(size_t)batch[row] * CC + col];
        c = fmaxf(c, 0.0f);
        const float o = A[row * CC + col];
        out[row * CC + col] = c + (o - mu) * rs * w_ + b_;
    }
}

// ---------------- launcher ----------------
extern "C" void kernel_launch(void* const* d_in, const int* in_sizes, int n_in,
                              void* d_out, int out_size)
{
    const float* orig       = (const float*)d_in[0];
    const float* dgf        = (const float*)d_in[1];
    const float* node_w     = (const float*)d_in[2];
    const float* node_b     = (const float*)d_in[3];
    const float* dg_w       = (const float*)d_in[4];
    const float* dg_b       = (const float*)d_in[5];
    const float* in_proj_w  = (const float*)d_in[6];
    const float* in_proj_b  = (const float*)d_in[7];
    const float* out_proj_w = (const float*)d_in[8];
    const float* out_proj_b = (const float*)d_in[9];
    const float* ffn_w      = (const float*)d_in[10];
    const float* ffn_b      = (const float*)d_in[11];
    const float* l1w        = (const float*)d_in[12];
    const float* l1b        = (const float*)d_in[13];
    const float* l2w        = (const float*)d_in[14];
    const float* l2b        = (const float*)d_in[15];
    const float* fuse_w     = (const float*)d_in[16];
    const float* fuse_b     = (const float*)d_in[17];
    const int*   batch      = (const int*)d_in[18];
    const int n = in_sizes[0] / CC;   // 262144

    float *G, *ATT, *Y, *H, *DG, *G2, *WVO, *BVO, *WF, *U, *V, *MU, *RS;
    cudaGetSymbolAddress((void**)&G,   g_G);
    cudaGetSymbolAddress((void**)&ATT, g_ATT);
    cudaGetSymbolAddress((void**)&Y,   g_Y);
    cudaGetSymbolAddress((void**)&H,   g_H);
    cudaGetSymbolAddress((void**)&DG,  g_DG);
    cudaGetSymbolAddress((void**)&G2,  g_G2);
    cudaGetSymbolAddress((void**)&WVO, g_WVO);
    cudaGetSymbolAddress((void**)&BVO, g_BVO);
    cudaGetSymbolAddress((void**)&WF,  g_WF);
    cudaGetSymbolAddress((void**)&U,   g_U);
    cudaGetSymbolAddress((void**)&V,   g_V);
    cudaGetSymbolAddress((void**)&MU,  g_MU);
    cudaGetSymbolAddress((void**)&RS,  g_RS);

    static bool attr_set = false;
    if (!attr_set) {
        cudaFuncSetAttribute(gemm_big, cudaFuncAttributeMaxDynamicSharedMemorySize, DSMEM_BYTES);
        attr_set = true;
    }

    const dim3 sg(CC / BN, PP / BM);   // (4, 32)

    // precomputes
    make_wvo<<<CC, CC>>>(out_proj_w, in_proj_w + 2 * CC * CC, in_proj_b + 2 * CC,
                         out_proj_b, WVO, BVO);
    prep_fuse<<<CC, CC>>>(fuse_w, node_w, node_b, WF, U, V);
    ln_stats<<<n / 8, 256>>>((const float4*)orig, MU, RS, n);

    // patch-level chain
    seg_mean_ln<<<PP, CC>>>(dgf, batch, n, dg_w, dg_b, G);
    gemm_small<false><<<sg, 256>>>(G, WVO, CC, ATT, BVO, nullptr);
    ln_rows<<<PP / 8, 256>>>(ATT, ffn_w, ffn_b, Y, PP);
    gemm_small<true ><<<sg, 256>>>(Y, l1w, CC, H, l1b, nullptr);
    gemm_small<false><<<sg, 256>>>(H, l2w, CC, DG, l2b, ATT);
    gemm_small<false><<<sg, 256>>>(DG, fuse_w + CC, 2 * CC, G2, fuse_b, nullptr);

    // node-level fused GEMM (raw orig in, final out)
    gemm_big<<<dim3(CC / GBN, n / GBM), 256, DSMEM_BYTES>>>(
        orig, WF, MU, RS, U, V, batch, G2, node_w, node_b, (float*)d_out);
}

// round 6
// speedup vs baseline: 1.4785x; 1.4785x over previous
#include <cuda_runtime.h>
#include <cuda_bf16.h>
#include <mma.h>
#include <cstdint>
#include <cstddef>

using namespace nvcuda;

#define CC 256
#define PP 4096
#define NN 262144

// ---------------- scratch (device globals: no allocation allowed) ----------------
static __device__ float g_G   [PP * CC];   // LN(segment mean of dg)
static __device__ float g_ATT [PP * CC];   // attn (= residual)
static __device__ float g_Y   [PP * CC];   // LN(attn)
static __device__ float g_H   [PP * CC];   // relu(y@W1.T+b1)
static __device__ float g_DG  [PP * CC];   // dg
static __device__ float g_G2  [PP * CC];   // dg@Wf2.T + fuse_b
static __device__ float g_WVO [CC * CC];   // out_proj_w @ Wv
static __device__ float g_BVO [CC];        // out_proj_w @ bv + bo
static __device__ float g_WF  [CC * CC];   // tf32-rounded W'[n,k] = node_w[k]*fuse_w1[n,k]
static __device__ float g_U   [CC];        // u[n] = sum_k W'[n,k]
static __device__ float g_V   [CC];        // v[n] = sum_k node_b[k]*fuse_w1[n,k]

// ---------------- cp.async helpers ----------------
__device__ __forceinline__ void cp_async16(void* smem, const void* gmem) {
    uint32_t s = (uint32_t)__cvta_generic_to_shared(smem);
    asm volatile("cp.async.cg.shared.global [%0], [%1], 16;\n" :: "r"(s), "l"(gmem));
}
#define CP_COMMIT() asm volatile("cp.async.commit_group;\n" ::: "memory")
#define CP_WAIT(n)  asm volatile("cp.async.wait_group %0;\n" :: "n"(n) : "memory")

// ---------------- fold Wvo = Wo @ Wv, bvo = Wo @ bv + bo ----------------
__global__ void make_wvo(const float* __restrict__ Wo, const float* __restrict__ Wv,
                         const float* __restrict__ bv, const float* __restrict__ bo,
                         float* __restrict__ Wvo, float* __restrict__ bvo)
{
    const int i = blockIdx.x;
    const int t = threadIdx.x;
    __shared__ float sWo[CC];
    __shared__ float red[CC];
    sWo[t] = Wo[i * CC + t];
    __syncthreads();
    float s = 0.f;
    #pragma unroll 8
    for (int j = 0; j < CC; j++) s += sWo[j] * Wv[j * CC + t];
    Wvo[i * CC + t] = s;
    red[t] = sWo[t] * bv[t];
    __syncthreads();
    for (int o = 128; o > 0; o >>= 1) {
        if (t < o) red[t] += red[t + o];
        __syncthreads();
    }
    if (t == 0) bvo[i] = red[0] + bo[i];
}

// ---------------- W' = tf32(node_w ∘ fuse_w1); u = rowsum(W'); v = node_b @ fuse_w1.T ----------------
__global__ void prep_fuse(const float* __restrict__ fuse_w, const float* __restrict__ nw,
                          const float* __restrict__ nb,
                          float* __restrict__ Wp, float* __restrict__ u, float* __restrict__ v)
{
    const int n = blockIdx.x;
    const int k = threadIdx.x;
    __shared__ float r1[CC], r2[CC];
    const float fw = fuse_w[(size_t)n * 2 * CC + k];   // first-half column k
    const float wv = wmma::__float_to_tf32(nw[k] * fw);
    Wp[n * CC + k] = wv;
    r1[k] = wv;
    r2[k] = nb[k] * fw;
    __syncthreads();
    for (int o = 128; o > 0; o >>= 1) {
        if (k < o) { r1[k] += r1[k + o]; r2[k] += r2[k + o]; }
        __syncthreads();
    }
    if (k == 0) { u[n] = r1[0]; v[n] = r2[0]; }
}

// ---------------- segment mean (sorted batch) fused with dg LayerNorm ----------------
__global__ void seg_mean_ln(const float* __restrict__ dg, const int* __restrict__ batch, int n,
                            const float* __restrict__ w, const float* __restrict__ b,
                            float* __restrict__ gout)
{
    const int p = blockIdx.x;
    const int t = threadIdx.x;
    __shared__ int sb[2];
    __shared__ float red[CC];
    if (t < 2) {
        int target = p + t;
        int lo = 0, hi = n;
        while (lo < hi) {
            int mid = (lo + hi) >> 1;
            if (batch[mid] < target) lo = mid + 1; else hi = mid;
        }
        sb[t] = lo;
    }
    __syncthreads();
    const int start = sb[0], end = sb[1];
    // 4-way unrolled accumulation: 4 independent loads in flight
    float s0 = 0.f, s1 = 0.f, s2 = 0.f, s3 = 0.f;
    int r = start;
    for (; r + 4 <= end; r += 4) {
        s0 += dg[(size_t)(r + 0) * CC + t];
        s1 += dg[(size_t)(r + 1) * CC + t];
        s2 += dg[(size_t)(r + 2) * CC + t];
        s3 += dg[(size_t)(r + 3) * CC + t];
    }
    for (; r < end; r++) s0 += dg[(size_t)r * CC + t];
    float s = (s0 + s1) + (s2 + s3);
    const int cnt = end - start;
    float mv = (cnt > 0) ? s / (float)cnt : 0.f;

    red[t] = mv; __syncthreads();
    for (int o = 128; o > 0; o >>= 1) { if (t < o) red[t] += red[t + o]; __syncthreads(); }
    const float mu = red[0] * (1.f / CC);
    __syncthreads();
    red[t] = mv * mv; __syncthreads();
    for (int o = 128; o > 0; o >>= 1) { if (t < o) red[t] += red[t + o]; __syncthreads(); }
    const float var = red[0] * (1.f / CC) - mu * mu;
    const float rstd = rsqrtf(var + 1e-5f);
    gout[(size_t)p * CC + t] = (mv - mu) * rstd * w[t] + b[t];
}

// ---------------- warp-per-row LayerNorm (P rows only) ----------------
__global__ void ln_rows(const float* __restrict__ in, const float* __restrict__ w,
                        const float* __restrict__ b, float* __restrict__ out, int rows)
{
    const int warp = blockIdx.x * (blockDim.x >> 5) + (threadIdx.x >> 5);
    if (warp >= rows) return;
    const int lane = threadIdx.x & 31;
    const float* rp = in + (size_t)warp * CC;
    float v[8];
    float s = 0.f, s2 = 0.f;
    #pragma unroll
    for (int i = 0; i < 8; i++) {
        v[i] = rp[lane + 32 * i];
        s  += v[i];
        s2 += v[i] * v[i];
    }
    #pragma unroll
    for (int o = 16; o > 0; o >>= 1) {
        s  += __shfl_xor_sync(0xFFFFFFFFu, s,  o);
        s2 += __shfl_xor_sync(0xFFFFFFFFu, s2, o);
    }
    const float mu  = s * (1.f / CC);
    const float var = s2 * (1.f / CC) - mu * mu;
    const float rstd = rsqrtf(var + 1e-5f);
    float* op = out + (size_t)warp * CC;
    #pragma unroll
    for (int i = 0; i < 8; i++) {
        const int c = lane + 32 * i;
        op[c] = (v[i] - mu) * rstd * w[c] + b[c];
    }
}

// ---------------- small tf32 GEMM (P-row chain): C = A @ B.T + epilogue ----------------
constexpr int BM = 128, BN = 64, BK = 32;
constexpr int LA = BK + 4;
constexpr int LC = BN + 4;

template<bool RELU>
__global__ __launch_bounds__(256)
void gemm_small(const float* __restrict__ A,
                const float* __restrict__ B, int ldb,
                float* __restrict__ C,
                const float* __restrict__ bias,
                const float* __restrict__ res)
{
    __shared__ __align__(16) float smem[BM * LC];
    float* As = smem;
    float* Bs = smem + BM * LA;

    const int tid = threadIdx.x;
    const int warpId = tid >> 5;
    const int wm = warpId & 3;
    const int wn = warpId >> 2;
    const size_t gm = (size_t)blockIdx.y * BM;
    const int gn = blockIdx.x * BN;

    wmma::fragment<wmma::accumulator, 16, 16, 8, float> acc[2][2];
    #pragma unroll
    for (int i = 0; i < 2; i++)
        #pragma unroll
        for (int j = 0; j < 2; j++)
            wmma::fill_fragment(acc[i][j], 0.0f);

    const int lr = tid >> 3;
    const int lc = (tid & 7) << 2;

    for (int k0 = 0; k0 < CC; k0 += BK) {
        __syncthreads();
        #pragma unroll
        for (int p = 0; p < 4; p++) {
            const int r = lr + 32 * p;
            float4 v = *reinterpret_cast<const float4*>(A + (gm + r) * CC + k0 + lc);
            v.x = wmma::__float_to_tf32(v.x); v.y = wmma::__float_to_tf32(v.y);
            v.z = wmma::__float_to_tf32(v.z); v.w = wmma::__float_to_tf32(v.w);
            *reinterpret_cast<float4*>(&As[r * LA + lc]) = v;
        }
        #pragma unroll
        for (int p = 0; p < 2; p++) {
            const int r = lr + 32 * p;
            float4 v = *reinterpret_cast<const float4*>(B + (size_t)(gn + r) * ldb + k0 + lc);
            v.x = wmma::__float_to_tf32(v.x); v.y = wmma::__float_to_tf32(v.y);
            v.z = wmma::__float_to_tf32(v.z); v.w = wmma::__float_to_tf32(v.w);
            *reinterpret_cast<float4*>(&Bs[r * LA + lc]) = v;
        }
        __syncthreads();
        #pragma unroll
        for (int kk = 0; kk < BK; kk += 8) {
            wmma::fragment<wmma::matrix_a, 16, 16, 8, wmma::precision::tf32, wmma::row_major> af[2];
            wmma::fragment<wmma::matrix_b, 16, 16, 8, wmma::precision::tf32, wmma::col_major> bf[2];
            #pragma unroll
            for (int i = 0; i < 2; i++)
                wmma::load_matrix_sync(af[i], &As[(wm * 32 + 16 * i) * LA + kk], LA);
            #pragma unroll
            for (int j = 0; j < 2; j++)
                wmma::load_matrix_sync(bf[j], &Bs[(wn * 32 + 16 * j) * LA + kk], LA);
            #pragma unroll
            for (int i = 0; i < 2; i++)
                #pragma unroll
                for (int j = 0; j < 2; j++)
                    wmma::mma_sync(acc[i][j], af[i], bf[j], acc[i][j]);
        }
    }
    __syncthreads();
    #pragma unroll
    for (int i = 0; i < 2; i++)
        #pragma unroll
        for (int j = 0; j < 2; j++)
            wmma::store_matrix_sync(&smem[(wm * 32 + 16 * i) * LC + wn * 32 + 16 * j],
                                    acc[i][j], LC, wmma::mem_row_major);
    __syncthreads();

    const int ec = tid & 63;
    const int er = tid >> 6;
    #pragma unroll 4
    for (int r = er; r < BM; r += 4) {
        float c = smem[r * LC + ec];
        const size_t row = gm + r;
        const int col = gn + ec;
        if (bias) c += bias[col];
        if (res)  c += res[row * CC + col];
        if (RELU) c = fmaxf(c, 0.0f);
        C[row * CC + col] = c;
    }
}

// ---------------- BIG GEMM: R4 tile shape + cp.async double buffer + fused LN stats ----------------
// out[row,col] = relu( rs_r*(orig@W'.T) - rs_r*mu_r*u[col] + v[col] + g2[batch[row],col] )
//               + (orig[row,col]-mu_r)*rs_r*nw[col] + nb[col]
constexpr int GBM = 128, GBN = 64, GBK = 32;
constexpr int GLA = GBK + 4;                   // 36
constexpr int GSTG = (GBM + GBN) * GLA;        // 6912 floats per stage
constexpr int GEPILD = GBN + 4;                // 68
constexpr int GDSMEM = (2 * GSTG + 2 * GBM) * 4;   // 56320 B (stages + mu/rs arrays)

__global__ __launch_bounds__(256)
void gemm_big(const float* __restrict__ A,     // orig [N,256] raw
              const float* __restrict__ Bw,    // W' [256,256] tf32-rounded
              const float* __restrict__ uvec, const float* __restrict__ vvec,
              const int*   __restrict__ batch, const float* __restrict__ g2,
              const float* __restrict__ nw, const float* __restrict__ nb,
              float* __restrict__ out)
{
    extern __shared__ __align__(16) float dsm[];
    float* smu = dsm + 2 * GSTG;   // [128]
    float* srs = smu + GBM;        // [128]

    const int tid = threadIdx.x;
    const int warpId = tid >> 5;
    const int wm = warpId & 3;     // 4 row groups × 32 rows
    const int wn = warpId >> 2;    // 2 col groups × 32 cols
    const size_t gm = (size_t)blockIdx.y * GBM;
    const int gn = blockIdx.x * GBN;

    wmma::fragment<wmma::accumulator, 16, 16, 8, float> acc[2][2];
    #pragma unroll
    for (int i = 0; i < 2; i++)
        #pragma unroll
        for (int j = 0; j < 2; j++)
            wmma::fill_fragment(acc[i][j], 0.0f);

    // row-stat assignment: 2 threads per row, 16 consecutive floats each
    const int srow = tid >> 1;
    const int shalf = (tid & 1) << 4;
    float ss = 0.f, ss2 = 0.f;

    const int ldr = tid >> 3;           // 0..31
    const int ldc = (tid & 7) << 2;     // 0,4,...,28

    auto load_stage = [&](int s, int k0) {
        float* As = dsm + s * GSTG;
        float* Bs = As + GBM * GLA;
        #pragma unroll
        for (int p = 0; p < 4; p++) {   // A: 128 rows
            const int r = ldr + 32 * p;
            cp_async16(&As[r * GLA + ldc], A + (gm + r) * CC + k0 + ldc);
        }
        #pragma unroll
        for (int p = 0; p < 2; p++) {   // B: 64 rows
            const int r = ldr + 32 * p;
            cp_async16(&Bs[r * GLA + ldc], Bw + (size_t)(gn + r) * CC + k0 + ldc);
        }
    };

    load_stage(0, 0);
    CP_COMMIT();

    #pragma unroll 1
    for (int kt = 0; kt < CC / GBK; kt++) {
        if (kt + 1 < CC / GBK) {
            load_stage((kt + 1) & 1, (kt + 1) * GBK);
            CP_COMMIT();
            CP_WAIT(1);
        } else {
            CP_WAIT(0);
        }
        __syncthreads();

        float* As = dsm + (kt & 1) * GSTG;
        float* Bs = As + GBM * GLA;

        // fused LN statistics over this 32-col chunk (FMA pipe, overlaps tensor)
        #pragma unroll
        for (int q = 0; q < 4; q++) {
            float4 v = *reinterpret_cast<const float4*>(&As[srow * GLA + shalf + 4 * q]);
            ss  += v.x + v.y + v.z + v.w;
            ss2 += v.x * v.x + v.y * v.y + v.z * v.z + v.w * v.w;
        }

        #pragma unroll
        for (int kk = 0; kk < GBK; kk += 8) {
            wmma::fragment<wmma::matrix_a, 16, 16, 8, wmma::precision::tf32, wmma::row_major> af[2];
            wmma::fragment<wmma::matrix_b, 16, 16, 8, wmma::precision::tf32, wmma::col_major> bf[2];
            #pragma unroll
            for (int i = 0; i < 2; i++) {
                wmma::load_matrix_sync(af[i], &As[(wm * 32 + 16 * i) * GLA + kk], GLA);
                #pragma unroll
                for (int e = 0; e < af[i].num_elements; e++)
                    af[i].x[e] = wmma::__float_to_tf32(af[i].x[e]);  // A rounded; B pre-rounded
            }
            #pragma unroll
            for (int j = 0; j < 2; j++)
                wmma::load_matrix_sync(bf[j], &Bs[(wn * 32 + 16 * j) * GLA + kk], GLA);
            #pragma unroll
            for (int i = 0; i < 2; i++)
                #pragma unroll
                for (int j = 0; j < 2; j++)
                    wmma::mma_sync(acc[i][j], af[i], bf[j], acc[i][j]);
        }
        __syncthreads();
    }

    // finalize per-row LN stats
    ss  += __shfl_xor_sync(0xFFFFFFFFu, ss,  1);
    ss2 += __shfl_xor_sync(0xFFFFFFFFu, ss2, 1);
    if ((tid & 1) == 0) {
        const float m = ss * (1.f / CC);
        smu[srow] = m;
        srs[srow] = rsqrtf(ss2 * (1.f / CC) - m * m + 1e-5f);
    }
    __syncthreads();

    // epilogue: acc -> smem (reuses stage 0) -> fused LN/gather/relu/residual -> out
    #pragma unroll
    for (int i = 0; i < 2; i++)
        #pragma unroll
        for (int j = 0; j < 2; j++)
            wmma::store_matrix_sync(&dsm[(wm * 32 + 16 * i) * GEPILD + wn * 32 + 16 * j],
                                    acc[i][j], GEPILD, wmma::mem_row_major);
    __syncthreads();

    const int ec = tid & 63;
    const int col = gn + ec;
    const float un = uvec[col], vn = vvec[col];
    const float w_ = nw[col],  b_ = nb[col];
    #pragma unroll 4
    for (int r = tid >> 6; r < GBM; r += 4) {
        const size_t row = gm + r;
        const float m = smu[r], rs = srs[r];
        float c = dsm[r * GEPILD + ec] * rs - m * rs * un + vn
                + g2[(size_t)batch[row] * CC + col];
        c = fmaxf(c, 0.0f);
        const float o = A[row * CC + col];   // L2-hot: streamed by this CTA moments ago
        out[row * CC + col] = c + (o - m) * rs * w_ + b_;
    }
}

// ---------------- launcher ----------------
extern "C" void kernel_launch(void* const* d_in, const int* in_sizes, int n_in,
                              void* d_out, int out_size)
{
    const float* orig       = (const float*)d_in[0];
    const float* dgf        = (const float*)d_in[1];
    const float* node_w     = (const float*)d_in[2];
    const float* node_b     = (const float*)d_in[3];
    const float* dg_w       = (const float*)d_in[4];
    const float* dg_b       = (const float*)d_in[5];
    const float* in_proj_w  = (const float*)d_in[6];
    const float* in_proj_b  = (const float*)d_in[7];
    const float* out_proj_w = (const float*)d_in[8];
    const float* out_proj_b = (const float*)d_in[9];
    const float* ffn_w      = (const float*)d_in[10];
    const float* ffn_b      = (const float*)d_in[11];
    const float* l1w        = (const float*)d_in[12];
    const float* l1b        = (const float*)d_in[13];
    const float* l2w        = (const float*)d_in[14];
    const float* l2b        = (const float*)d_in[15];
    const float* fuse_w     = (const float*)d_in[16];
    const float* fuse_b     = (const float*)d_in[17];
    const int*   batch      = (const int*)d_in[18];
    const int n = in_sizes[0] / CC;   // 262144

    float *G, *ATT, *Y, *H, *DG, *G2, *WVO, *BVO, *WF, *U, *V;
    cudaGetSymbolAddress((void**)&G,   g_G);
    cudaGetSymbolAddress((void**)&ATT, g_ATT);
    cudaGetSymbolAddress((void**)&Y,   g_Y);
    cudaGetSymbolAddress((void**)&H,   g_H);
    cudaGetSymbolAddress((void**)&DG,  g_DG);
    cudaGetSymbolAddress((void**)&G2,  g_G2);
    cudaGetSymbolAddress((void**)&WVO, g_WVO);
    cudaGetSymbolAddress((void**)&BVO, g_BVO);
    cudaGetSymbolAddress((void**)&WF,  g_WF);
    cudaGetSymbolAddress((void**)&U,   g_U);
    cudaGetSymbolAddress((void**)&V,   g_V);

    cudaFuncSetAttribute(gemm_big, cudaFuncAttributeMaxDynamicSharedMemorySize, GDSMEM);

    const dim3 sg(CC / BN, PP / BM);   // (4, 32)

    // precomputes
    make_wvo<<<CC, CC>>>(out_proj_w, in_proj_w + 2 * CC * CC, in_proj_b + 2 * CC,
                         out_proj_b, WVO, BVO);
    prep_fuse<<<CC, CC>>>(fuse_w, node_w, node_b, WF, U, V);

    // patch-level chain
    seg_mean_ln<<<PP, CC>>>(dgf, batch, n, dg_w, dg_b, G);
    gemm_small<false><<<sg, 256>>>(G, WVO, CC, ATT, BVO, nullptr);
    ln_rows<<<PP / 8, 256>>>(ATT, ffn_w, ffn_b, Y, PP);
    gemm_small<true ><<<sg, 256>>>(Y, l1w, CC, H, l1b, nullptr);
    gemm_small<false><<<sg, 256>>>(H, l2w, CC, DG, l2b, ATT);
    gemm_small<false><<<sg, 256>>>(DG, fuse_w + CC, 2 * CC, G2, fuse_b, nullptr);

    // node-level fused GEMM (raw orig in, final out; LN stats fused in-kernel)
    gemm_big<<<dim3(CC / GBN, n / GBM), 256, GDSMEM>>>(
        orig, WF, U, V, batch, G2, node_w, node_b, (float*)d_out);
}

// round 8
// speedup vs baseline: 1.4796x; 1.0008x over previous
#include <cuda_runtime.h>
#include <cuda_bf16.h>
#include <mma.h>
#include <cstdint>
#include <cstddef>

using namespace nvcuda;

#define CC 256
#define PP 4096
#define NN 262144

// ---------------- scratch (device globals: no allocation allowed) ----------------
static __device__ float g_G   [PP * CC];   // LN(segment mean of dg)
static __device__ float g_ATT [PP * CC];   // attn (= residual)
static __device__ float g_Y   [PP * CC];   // LN(attn)
static __device__ float g_H   [PP * CC];   // relu(y@W1.T+b1)
static __device__ float g_G2  [PP * CC];   // H@M1.T + ATT@Wf2.T + bias2
static __device__ float g_WVO [CC * CC];   // out_proj_w @ Wv
static __device__ float g_BVO [CC];        // out_proj_w @ bv + bo
static __device__ float g_M1  [CC * CC];   // Wf2 @ l2w
static __device__ float g_B2  [CC];        // Wf2 @ l2b + fuse_b
static __device__ float g_WF  [CC * CC];   // tf32-rounded W'[n,k] = node_w[k]*fuse_w1[n,k]
static __device__ float g_U   [CC];        // rowsum(W')
static __device__ float g_V   [CC];        // node_b @ fuse_w1.T

// ---------------- helpers ----------------
__device__ __forceinline__ uint32_t smem_u32(const void* p) {
    uint32_t a;
    asm("{ .reg .u64 t; cvta.to.shared.u64 t, %1; cvt.u32.u64 %0, t; }" : "=r"(a) : "l"(p));
    return a;
}
__device__ __forceinline__ void cp_async16(uint32_t smem, const void* gmem) {
    asm volatile("cp.async.cg.shared.global [%0], [%1], 16;\n" :: "r"(smem), "l"(gmem));
}
#define CP_COMMIT() asm volatile("cp.async.commit_group;\n" ::: "memory")
#define CP_WAIT(n)  asm volatile("cp.async.wait_group %0;\n" :: "n"(n) : "memory")

__device__ __forceinline__ uint32_t sw128(uint32_t b) { return b ^ ((b >> 3) & 0x70); }

__device__ __forceinline__ void ldsm4(uint32_t& r0, uint32_t& r1, uint32_t& r2, uint32_t& r3,
                                      uint32_t addr) {
    asm volatile("ldmatrix.sync.aligned.m8n8.x4.shared.b16 {%0,%1,%2,%3}, [%4];"
                 : "=r"(r0), "=r"(r1), "=r"(r2), "=r"(r3) : "r"(addr));
}
__device__ __forceinline__ void mma_tf32(float* d, uint32_t a0, uint32_t a1, uint32_t a2,
                                         uint32_t a3, uint32_t b0, uint32_t b1) {
    asm volatile(
        "mma.sync.aligned.m16n8k8.row.col.f32.tf32.tf32.f32 "
        "{%0,%1,%2,%3}, {%4,%5,%6,%7}, {%8,%9}, {%0,%1,%2,%3};"
        : "+f"(d[0]), "+f"(d[1]), "+f"(d[2]), "+f"(d[3])
        : "r"(a0), "r"(a1), "r"(a2), "r"(a3), "r"(b0), "r"(b1));
}

// ================ fused precompute + segment-mean kernel (launch 0) ================
// blocks [0,256): WVO/BVO   [256,512): M1/B2   [512,768): WF/U/V   [768,768+P): seg_mean
__global__ void fused_pre_seg(
    const float* __restrict__ out_proj_w, const float* __restrict__ in_proj_w,
    const float* __restrict__ in_proj_b,  const float* __restrict__ out_proj_b,
    const float* __restrict__ fuse_w,     const float* __restrict__ l2w,
    const float* __restrict__ l2b,        const float* __restrict__ fuse_b,
    const float* __restrict__ node_w,     const float* __restrict__ node_b,
    const float* __restrict__ dg,         const int* __restrict__ batch, int n,
    const float* __restrict__ dgw,        const float* __restrict__ dgb,
    float* __restrict__ WVO, float* __restrict__ BVO,
    float* __restrict__ M1,  float* __restrict__ B2,
    float* __restrict__ WF,  float* __restrict__ U, float* __restrict__ V,
    float* __restrict__ G)
{
    const int blk = blockIdx.x;
    const int t = threadIdx.x;
    __shared__ float r1[CC], r2[CC];

    if (blk < 512) {
        // generalized Wvo = Wo @ Wv ; bvo = Wo @ bv + bo
        const int i = (blk < 256) ? blk : blk - 256;
        const float* Wo  = (blk < 256) ? out_proj_w : (fuse_w + CC);          // Wf2 slice
        const int    lda = (blk < 256) ? CC : 2 * CC;
        const float* Wv  = (blk < 256) ? (in_proj_w + 2 * CC * CC) : l2w;
        const float* bv  = (blk < 256) ? (in_proj_b + 2 * CC) : l2b;
        const float* bo  = (blk < 256) ? out_proj_b : fuse_b;
        float* Wout = (blk < 256) ? WVO : M1;
        float* bout = (blk < 256) ? BVO : B2;

        r1[t] = Wo[(size_t)i * lda + t];
        __syncthreads();
        float s = 0.f;
        #pragma unroll 8
        for (int j = 0; j < CC; j++) s += r1[j] * Wv[j * CC + t];
        Wout[i * CC + t] = s;
        r2[t] = r1[t] * bv[t];
        __syncthreads();
        for (int o = 128; o > 0; o >>= 1) {
            if (t < o) r2[t] += r2[t + o];
            __syncthreads();
        }
        if (t == 0) bout[i] = r2[0] + bo[i];
    } else if (blk < 768) {
        // WF = tf32(node_w ∘ fuse_w1); U = rowsum; V = node_b @ fuse_w1.T
        const int i = blk - 512;
        const float fw = fuse_w[(size_t)i * 2 * CC + t];
        const float wv = wmma::__float_to_tf32(node_w[t] * fw);
        WF[i * CC + t] = wv;
        r1[t] = wv;
        r2[t] = node_b[t] * fw;
        __syncthreads();
        for (int o = 128; o > 0; o >>= 1) {
            if (t < o) { r1[t] += r1[t + o]; r2[t] += r2[t + o]; }
            __syncthreads();
        }
        if (t == 0) { U[i] = r1[0]; V[i] = r2[0]; }
    } else {
        // segment mean over sorted batch + dg LayerNorm
        const int p = blk - 768;
        __shared__ int sb[2];
        if (t < 2) {
            int target = p + t;
            int lo = 0, hi = n;
            while (lo < hi) {
                int mid = (lo + hi) >> 1;
                if (batch[mid] < target) lo = mid + 1; else hi = mid;
            }
            sb[t] = lo;
        }
        __syncthreads();
        const int start = sb[0], end = sb[1];
        float s0 = 0.f, s1 = 0.f, s2 = 0.f, s3 = 0.f;
        int r = start;
        for (; r + 4 <= end; r += 4) {
            s0 += dg[(size_t)(r + 0) * CC + t];
            s1 += dg[(size_t)(r + 1) * CC + t];
            s2 += dg[(size_t)(r + 2) * CC + t];
            s3 += dg[(size_t)(r + 3) * CC + t];
        }
        for (; r < end; r++) s0 += dg[(size_t)r * CC + t];
        float s = (s0 + s1) + (s2 + s3);
        const int cnt = end - start;
        float mv = (cnt > 0) ? s / (float)cnt : 0.f;

        r1[t] = mv; __syncthreads();
        for (int o = 128; o > 0; o >>= 1) { if (t < o) r1[t] += r1[t + o]; __syncthreads(); }
        const float mu = r1[0] * (1.f / CC);
        __syncthreads();
        r1[t] = mv * mv; __syncthreads();
        for (int o = 128; o > 0; o >>= 1) { if (t < o) r1[t] += r1[t + o]; __syncthreads(); }
        const float var = r1[0] * (1.f / CC) - mu * mu;
        const float rstd = rsqrtf(var + 1e-5f);
        G[(size_t)p * CC + t] = (mv - mu) * rstd * dgw[t] + dgb[t];
    }
}

// ---------------- warp-per-row LayerNorm (P rows) ----------------
__global__ void ln_rows(const float* __restrict__ in, const float* __restrict__ w,
                        const float* __restrict__ b, float* __restrict__ out, int rows)
{
    const int warp = blockIdx.x * (blockDim.x >> 5) + (threadIdx.x >> 5);
    if (warp >= rows) return;
    const int lane = threadIdx.x & 31;
    const float* rp = in + (size_t)warp * CC;
    float v[8];
    float s = 0.f, s2 = 0.f;
    #pragma unroll
    for (int i = 0; i < 8; i++) {
        v[i] = rp[lane + 32 * i];
        s  += v[i];
        s2 += v[i] * v[i];
    }
    #pragma unroll
    for (int o = 16; o > 0; o >>= 1) {
        s  += __shfl_xor_sync(0xFFFFFFFFu, s,  o);
        s2 += __shfl_xor_sync(0xFFFFFFFFu, s2, o);
    }
    const float mu  = s * (1.f / CC);
    const float var = s2 * (1.f / CC) - mu * mu;
    const float rstd = rsqrtf(var + 1e-5f);
    float* op = out + (size_t)warp * CC;
    #pragma unroll
    for (int i = 0; i < 8; i++) {
        const int c = lane + 32 * i;
        op[c] = (v[i] - mu) * rstd * w[c] + b[c];
    }
}

// ---------------- small tf32 wmma GEMM: C = A1@B1.T [+ A2@B2.T] + bias, opt relu --------
constexpr int BM = 128, BN = 64, BK = 32;
constexpr int LA = BK + 4;
constexpr int LC = BN + 4;

template<bool RELU, bool CAT>
__global__ __launch_bounds__(256)
void gemm_small(const float* __restrict__ A1, const float* __restrict__ B1, int ldb1,
                const float* __restrict__ A2, const float* __restrict__ B2x, int ldb2,
                float* __restrict__ C, const float* __restrict__ bias)
{
    __shared__ __align__(16) float smem[BM * LC];
    float* As = smem;
    float* Bs = smem + BM * LA;

    const int tid = threadIdx.x;
    const int warpId = tid >> 5;
    const int wm = warpId & 3;
    const int wn = warpId >> 2;
    const size_t gm = (size_t)blockIdx.y * BM;
    const int gn = blockIdx.x * BN;

    wmma::fragment<wmma::accumulator, 16, 16, 8, float> acc[2][2];
    #pragma unroll
    for (int i = 0; i < 2; i++)
        #pragma unroll
        for (int j = 0; j < 2; j++)
            wmma::fill_fragment(acc[i][j], 0.0f);

    const int lr = tid >> 3;
    const int lc = (tid & 7) << 2;
    const int KTOT = CAT ? 2 * CC : CC;

    for (int kt = 0; kt < KTOT; kt += BK) {
        const bool second = CAT && (kt >= CC);
        const float* A = second ? A2 : A1;
        const float* B = second ? B2x : B1;
        const int ldb = second ? ldb2 : ldb1;
        const int k0 = second ? kt - CC : kt;
        __syncthreads();
        #pragma unroll
        for (int p = 0; p < 4; p++) {
            const int r = lr + 32 * p;
            float4 v = *reinterpret_cast<const float4*>(A + (gm + r) * CC + k0 + lc);
            v.x = wmma::__float_to_tf32(v.x); v.y = wmma::__float_to_tf32(v.y);
            v.z = wmma::__float_to_tf32(v.z); v.w = wmma::__float_to_tf32(v.w);
            *reinterpret_cast<float4*>(&As[r * LA + lc]) = v;
        }
        #pragma unroll
        for (int p = 0; p < 2; p++) {
            const int r = lr + 32 * p;
            float4 v = *reinterpret_cast<const float4*>(B + (size_t)(gn + r) * ldb + k0 + lc);
            v.x = wmma::__float_to_tf32(v.x); v.y = wmma::__float_to_tf32(v.y);
            v.z = wmma::__float_to_tf32(v.z); v.w = wmma::__float_to_tf32(v.w);
            *reinterpret_cast<float4*>(&Bs[r * LA + lc]) = v;
        }
        __syncthreads();
        #pragma unroll
        for (int kk = 0; kk < BK; kk += 8) {
            wmma::fragment<wmma::matrix_a, 16, 16, 8, wmma::precision::tf32, wmma::row_major> af[2];
            wmma::fragment<wmma::matrix_b, 16, 16, 8, wmma::precision::tf32, wmma::col_major> bf[2];
            #pragma unroll
            for (int i = 0; i < 2; i++)
                wmma::load_matrix_sync(af[i], &As[(wm * 32 + 16 * i) * LA + kk], LA);
            #pragma unroll
            for (int j = 0; j < 2; j++)
                wmma::load_matrix_sync(bf[j], &Bs[(wn * 32 + 16 * j) * LA + kk], LA);
            #pragma unroll
            for (int i = 0; i < 2; i++)
                #pragma unroll
                for (int j = 0; j < 2; j++)
                    wmma::mma_sync(acc[i][j], af[i], bf[j], acc[i][j]);
        }
    }
    __syncthreads();
    #pragma unroll
    for (int i = 0; i < 2; i++)
        #pragma unroll
        for (int j = 0; j < 2; j++)
            wmma::store_matrix_sync(&smem[(wm * 32 + 16 * i) * LC + wn * 32 + 16 * j],
                                    acc[i][j], LC, wmma::mem_row_major);
    __syncthreads();

    const int ec = tid & 63;
    const int er = tid >> 6;
    #pragma unroll 4
    for (int r = er; r < BM; r += 4) {
        float c = smem[r * LC + ec] + bias[gn + ec];
        if (RELU) c = fmaxf(c, 0.0f);
        C[(gm + r) * CC + gn + ec] = c;
    }
}

// ================= BIG GEMM: hand-rolled tf32 mma + ldmatrix (sm80-path) =================
// CTA 128x128, BK=32, 8 warps (2 row-blocks of 64 x 4 col-blocks of 32), 2-stage cp.async.
// out[row,col] = relu( rs_r*(orig@W'.T) - rs_r*mu_r*u[col] + v[col] + g2[batch[row],col] )
//               + (orig[row,col]-mu_r)*rs_r*nw[col] + nb[col]
constexpr int QSTAGE = 32768;                  // A 16KB + B 16KB per stage
constexpr int EPILD  = 136;
constexpr int SM_MU_OFF = 128 * EPILD * 4;     // 69632
constexpr int SM_RS_OFF = SM_MU_OFF + 512;
constexpr int SM_BIG    = SM_RS_OFF + 512;     // 70656

__global__ __launch_bounds__(256)
void gemm_big_mma(const float* __restrict__ A,     // orig [N,256] raw fp32
                  const float* __restrict__ Bw,    // W' [256,256] tf32 values
                  const float* __restrict__ uvec, const float* __restrict__ vvec,
                  const int*   __restrict__ batch, const float* __restrict__ g2,
                  const float* __restrict__ nw, const float* __restrict__ nbv,
                  float* __restrict__ out)
{
    extern __shared__ __align__(1024) char smc[];
    const uint32_t sb = smem_u32(smc);
    const int tid  = threadIdx.x;
    const int wid  = tid >> 5;
    const int lane = tid & 31;
    const size_t gm = (size_t)blockIdx.y * 128;
    const int gn = blockIdx.x * 128;
    const int wm = wid & 1;        // row block (64 rows)
    const int wn = wid >> 1;       // col block (32 cols)

    float acc[4][4][4];
    #pragma unroll
    for (int i = 0; i < 4; i++)
        #pragma unroll
        for (int j = 0; j < 4; j++)
            #pragma unroll
            for (int e = 0; e < 4; e++) acc[i][j][e] = 0.f;

    // cp.async loader: 32 rows x 8 chunks per pass, 4 passes for 128 rows
    const int lr = tid >> 3, lc16 = tid & 7;
    auto load_stage = [&](int s, int k0) {
        const uint32_t a0 = sb + s * QSTAGE;
        const uint32_t b0 = a0 + 16384;
        #pragma unroll
        for (int p = 0; p < 4; p++) {
            const int r = lr + 32 * p;
            cp_async16(a0 + sw128(r * 128 + lc16 * 16), A + (gm + r) * CC + k0 + lc16 * 4);
        }
        #pragma unroll
        for (int p = 0; p < 4; p++) {
            const int r = lr + 32 * p;
            cp_async16(b0 + sw128(r * 128 + lc16 * 16), Bw + (size_t)(gn + r) * CC + k0 + lc16 * 4);
        }
    };

    // ldmatrix lane-address components
    const int aRow = lane & 15;
    const int aKb  = (lane >> 4) * 16;            // +0 or +16 bytes (k +0 / +4)
    const int bN   = ((lane >> 4) << 3) + (lane & 7);
    const int bKb  = ((lane >> 3) & 1) * 16;

    // fused LN-stat assignment: 2 threads per row, 16 floats each per chunk
    const int srow  = tid >> 1;
    const int shalf = tid & 1;
    float ss = 0.f, ss2 = 0.f;

    load_stage(0, 0);
    CP_COMMIT();

    #pragma unroll 1
    for (int kt = 0; kt < 8; kt++) {
        if (kt < 7) {
            load_stage((kt + 1) & 1, (kt + 1) * 32);
            CP_COMMIT();
            CP_WAIT(1);
        } else {
            CP_WAIT(0);
        }
        __syncthreads();

        const uint32_t abase = sb + (kt & 1) * QSTAGE;
        const uint32_t bbase = abase + 16384;

        // LN statistics (FMA pipe, overlaps tensor work)
        #pragma unroll
        for (int q = 0; q < 2; q++) {
            const float4 v = *reinterpret_cast<const float4*>(
                smc + (kt & 1) * QSTAGE + sw128(srow * 128 + shalf * 64 + q * 32 + 0));
            const float4 u = *reinterpret_cast<const float4*>(
                smc + (kt & 1) * QSTAGE + sw128(srow * 128 + shalf * 64 + q * 32 + 16));
            ss  += (v.x + v.y) + (v.z + v.w) + (u.x + u.y) + (u.z + u.w);
            ss2 += v.x*v.x + v.y*v.y + v.z*v.z + v.w*v.w
                 + u.x*u.x + u.y*u.y + u.z*u.z + u.w*u.w;
        }

        #pragma unroll
        for (int kk = 0; kk < 4; kk++) {
            uint32_t av[4][4];
            #pragma unroll
            for (int mi = 0; mi < 4; mi++)
                ldsm4(av[mi][0], av[mi][1], av[mi][2], av[mi][3],
                      abase + sw128((wm * 64 + mi * 16 + aRow) * 128 + kk * 32 + aKb));
            uint32_t bv[2][4];
            #pragma unroll
            for (int nb = 0; nb < 2; nb++)
                ldsm4(bv[nb][0], bv[nb][1], bv[nb][2], bv[nb][3],
                      bbase + sw128((wn * 32 + nb * 16 + bN) * 128 + kk * 32 + bKb));
            #pragma unroll
            for (int mi = 0; mi < 4; mi++) {
                #pragma unroll
                for (int nb = 0; nb < 2; nb++) {
                    mma_tf32(acc[mi][nb * 2 + 0], av[mi][0], av[mi][1], av[mi][2], av[mi][3],
                             bv[nb][0], bv[nb][1]);
                    mma_tf32(acc[mi][nb * 2 + 1], av[mi][0], av[mi][1], av[mi][2], av[mi][3],
                             bv[nb][2], bv[nb][3]);
                }
            }
        }
        __syncthreads();
    }

    // finalize LN stats (partner thread tid^1 is in the same warp)
    ss  += __shfl_xor_sync(0xFFFFFFFFu, ss,  1);
    ss2 += __shfl_xor_sync(0xFFFFFFFFu, ss2, 1);
    if (shalf == 0) {
        const float m = ss * (1.f / CC);
        *reinterpret_cast<float*>(smc + SM_MU_OFF + srow * 4) = m;
        *reinterpret_cast<float*>(smc + SM_RS_OFF + srow * 4) =
            rsqrtf(ss2 * (1.f / CC) - m * m + 1e-5f);
    }
    __syncthreads();   // all smem tile reads done before epi overwrite

    // acc -> epilogue smem (d0,d1 = (row, col..col+1); d2,d3 = (row+8, ...))
    {
        float* ep = reinterpret_cast<float*>(smc);
        const int r0 = lane >> 2;
        const int c0 = (lane & 3) * 2;
        #pragma unroll
        for (int mi = 0; mi < 4; mi++) {
            const int rb = wm * 64 + mi * 16 + r0;
            #pragma unroll
            for (int ni = 0; ni < 4; ni++) {
                const int cb = wn * 32 + ni * 8 + c0;
                *reinterpret_cast<float2*>(ep + rb * EPILD + cb) =
                    make_float2(acc[mi][ni][0], acc[mi][ni][1]);
                *reinterpret_cast<float2*>(ep + (rb + 8) * EPILD + cb) =
                    make_float2(acc[mi][ni][2], acc[mi][ni][3]);
            }
        }
    }
    __syncthreads();

    // fused epilogue
    {
        const float* ep  = reinterpret_cast<const float*>(smc);
        const float* smu = reinterpret_cast<const float*>(smc + SM_MU_OFF);
        const float* srs = reinterpret_cast<const float*>(smc + SM_RS_OFF);
        const int ec = tid & 127;
        const int col = gn + ec;
        const float un = uvec[col], vn = vvec[col];
        const float w_ = nw[col],  b_ = nbv[col];
        #pragma unroll 4
        for (int r = tid >> 7; r < 128; r += 2) {
            const size_t row = gm + r;
            const float m = smu[r], rs = srs[r];
            float c = ep[r * EPILD + ec] * rs - m * rs * un + vn
                    + g2[(size_t)batch[row] * CC + col];
            c = fmaxf(c, 0.0f);
            const float o = A[row * CC + col];   // L2-hot reload
            out[row * CC + col] = c + (o - m) * rs * w_ + b_;
        }
    }
}

// ---------------- launcher ----------------
extern "C" void kernel_launch(void* const* d_in, const int* in_sizes, int n_in,
                              void* d_out, int out_size)
{
    const float* orig       = (const float*)d_in[0];
    const float* dgf        = (const float*)d_in[1];
    const float* node_w     = (const float*)d_in[2];
    const float* node_b     = (const float*)d_in[3];
    const float* dg_w       = (const float*)d_in[4];
    const float* dg_b       = (const float*)d_in[5];
    const float* in_proj_w  = (const float*)d_in[6];
    const float* in_proj_b  = (const float*)d_in[7];
    const float* out_proj_w = (const float*)d_in[8];
    const float* out_proj_b = (const float*)d_in[9];
    const float* ffn_w      = (const float*)d_in[10];
    const float* ffn_b      = (const float*)d_in[11];
    const float* l1w        = (const float*)d_in[12];
    const float* l1b        = (const float*)d_in[13];
    const float* l2w        = (const float*)d_in[14];
    const float* l2b        = (const float*)d_in[15];
    const float* fuse_w     = (const float*)d_in[16];
    const float* fuse_b     = (const float*)d_in[17];
    const int*   batch      = (const int*)d_in[18];
    const int n = in_sizes[0] / CC;   // 262144

    float *G, *ATT, *Y, *H, *G2, *WVO, *BVO, *M1, *B2, *WF, *U, *V;
    cudaGetSymbolAddress((void**)&G,   g_G);
    cudaGetSymbolAddress((void**)&ATT, g_ATT);
    cudaGetSymbolAddress((void**)&Y,   g_Y);
    cudaGetSymbolAddress((void**)&H,   g_H);
    cudaGetSymbolAddress((void**)&G2,  g_G2);
    cudaGetSymbolAddress((void**)&WVO, g_WVO);
    cudaGetSymbolAddress((void**)&BVO, g_BVO);
    cudaGetSymbolAddress((void**)&M1,  g_M1);
    cudaGetSymbolAddress((void**)&B2,  g_B2);
    cudaGetSymbolAddress((void**)&WF,  g_WF);
    cudaGetSymbolAddress((void**)&U,   g_U);
    cudaGetSymbolAddress((void**)&V,   g_V);

    cudaFuncSetAttribute(gemm_big_mma, cudaFuncAttributeMaxDynamicSharedMemorySize, SM_BIG);

    const dim3 sg(CC / BN, PP / BM);   // (4, 32)

    // 0: all precomputes + segment-mean/LN (one kernel)
    fused_pre_seg<<<768 + PP, 256>>>(
        out_proj_w, in_proj_w, in_proj_b, out_proj_b,
        fuse_w, l2w, l2b, fuse_b, node_w, node_b,
        dgf, batch, n, dg_w, dg_b,
        WVO, BVO, M1, B2, WF, U, V, G);
    // 1: ATT = G @ WVO.T + BVO
    gemm_small<false, false><<<sg, 256>>>(G, WVO, CC, nullptr, nullptr, 0, ATT, BVO);
    // 2: Y = LN(ATT)
    ln_rows<<<PP / 8, 256>>>(ATT, ffn_w, ffn_b, Y, PP);
    // 3: H = relu(Y @ l1w.T + l1b)
    gemm_small<true, false><<<sg, 256>>>(Y, l1w, CC, nullptr, nullptr, 0, H, l1b);
    // 4: G2 = H @ M1.T + ATT @ Wf2.T + B2   (K=512 concat GEMM; DG eliminated)
    gemm_small<false, true><<<sg, 256>>>(H, M1, CC, ATT, fuse_w + CC, 2 * CC, G2, B2);
    // 5: big fused node GEMM (profiled launch)
    gemm_big_mma<<<dim3(2, n / 128), 256, SM_BIG>>>(
        orig, WF, U, V, batch, G2, node_w, node_b, (float*)d_out);
}

// round 9
// speedup vs baseline: 2.5262x; 1.7073x over previous
#include <cuda_runtime.h>
#include <cuda_fp16.h>
#include <cuda_bf16.h>
#include <mma.h>
#include <cstdint>
#include <cstddef>

using namespace nvcuda;

#define CC 256
#define PP 4096
#define NN 262144

// ---------------- scratch (device globals: no allocation allowed) ----------------
static __device__ float g_G   [PP * CC];   // LN(segment mean of dg)
static __device__ float g_ATT [PP * CC];   // attn (= residual)
static __device__ float g_Y   [PP * CC];   // LN(attn)
static __device__ float g_H   [PP * CC];   // relu(y@W1.T+b1)
static __device__ float g_G2  [PP * CC];   // H@M1.T + ATT@Wf2.T + bias2
static __device__ float g_WVO [CC * CC];   // out_proj_w @ Wv
static __device__ float g_BVO [CC];        // out_proj_w @ bv + bo
static __device__ float g_M1  [CC * CC];   // Wf2 @ l2w
static __device__ float g_B2  [CC];        // Wf2 @ l2b + fuse_b
static __device__ __half g_WFh[CC * CC];   // fp16 W'[n,k] = node_w[k]*fuse_w1[n,k]
static __device__ float g_U   [CC];        // rowsum(fp16 W')
static __device__ float g_V   [CC];        // node_b @ fuse_w1.T

// ---------------- helpers ----------------
__device__ __forceinline__ uint32_t smem_u32(const void* p) {
    uint32_t a;
    asm("{ .reg .u64 t; cvta.to.shared.u64 t, %1; cvt.u32.u64 %0, t; }" : "=r"(a) : "l"(p));
    return a;
}
__device__ __forceinline__ void cp_async16(uint32_t smem, const void* gmem) {
    asm volatile("cp.async.cg.shared.global [%0], [%1], 16;\n" :: "r"(smem), "l"(gmem));
}
#define CP_COMMIT() asm volatile("cp.async.commit_group;\n" ::: "memory")
#define CP_WAIT(n)  asm volatile("cp.async.wait_group %0;\n" :: "n"(n) : "memory")

__device__ __forceinline__ void ldsm4(uint32_t& r0, uint32_t& r1, uint32_t& r2, uint32_t& r3,
                                      uint32_t addr) {
    asm volatile("ldmatrix.sync.aligned.m8n8.x4.shared.b16 {%0,%1,%2,%3}, [%4];"
                 : "=r"(r0), "=r"(r1), "=r"(r2), "=r"(r3) : "r"(addr));
}
__device__ __forceinline__ void mma_f16(float* d, uint32_t a0, uint32_t a1, uint32_t a2,
                                        uint32_t a3, uint32_t b0, uint32_t b1) {
    asm volatile(
        "mma.sync.aligned.m16n8k16.row.col.f32.f16.f16.f32 "
        "{%0,%1,%2,%3}, {%4,%5,%6,%7}, {%8,%9}, {%0,%1,%2,%3};"
        : "+f"(d[0]), "+f"(d[1]), "+f"(d[2]), "+f"(d[3])
        : "r"(a0), "r"(a1), "r"(a2), "r"(a3), "r"(b0), "r"(b1));
}

// ================ fused precompute + segment-mean kernel (launch 0) ================
// blocks [0,256): WVO/BVO   [256,512): M1/B2   [512,768): WFh/U/V   [768,768+P): seg_mean
__global__ void fused_pre_seg(
    const float* __restrict__ out_proj_w, const float* __restrict__ in_proj_w,
    const float* __restrict__ in_proj_b,  const float* __restrict__ out_proj_b,
    const float* __restrict__ fuse_w,     const float* __restrict__ l2w,
    const float* __restrict__ l2b,        const float* __restrict__ fuse_b,
    const float* __restrict__ node_w,     const float* __restrict__ node_b,
    const float* __restrict__ dg,         const int* __restrict__ batch, int n,
    const float* __restrict__ dgw,        const float* __restrict__ dgb,
    float* __restrict__ WVO, float* __restrict__ BVO,
    float* __restrict__ M1,  float* __restrict__ B2,
    __half* __restrict__ WFh, float* __restrict__ U, float* __restrict__ V,
    float* __restrict__ G)
{
    const int blk = blockIdx.x;
    const int t = threadIdx.x;
    __shared__ float r1[CC], r2[CC];

    if (blk < 512) {
        const int i = (blk < 256) ? blk : blk - 256;
        const float* Wo  = (blk < 256) ? out_proj_w : (fuse_w + CC);
        const int    lda = (blk < 256) ? CC : 2 * CC;
        const float* Wv  = (blk < 256) ? (in_proj_w + 2 * CC * CC) : l2w;
        const float* bv  = (blk < 256) ? (in_proj_b + 2 * CC) : l2b;
        const float* bo  = (blk < 256) ? out_proj_b : fuse_b;
        float* Wout = (blk < 256) ? WVO : M1;
        float* bout = (blk < 256) ? BVO : B2;

        r1[t] = Wo[(size_t)i * lda + t];
        __syncthreads();
        float s = 0.f;
        #pragma unroll 8
        for (int j = 0; j < CC; j++) s += r1[j] * Wv[j * CC + t];
        Wout[i * CC + t] = s;
        r2[t] = r1[t] * bv[t];
        __syncthreads();
        for (int o = 128; o > 0; o >>= 1) {
            if (t < o) r2[t] += r2[t + o];
            __syncthreads();
        }
        if (t == 0) bout[i] = r2[0] + bo[i];
    } else if (blk < 768) {
        // WFh = fp16(node_w ∘ fuse_w1); U = rowsum(fp16 vals); V = node_b @ fuse_w1.T
        const int i = blk - 512;
        const float fw = fuse_w[(size_t)i * 2 * CC + t];
        const __half hv = __float2half(node_w[t] * fw);
        WFh[i * CC + t] = hv;
        r1[t] = __half2float(hv);
        r2[t] = node_b[t] * fw;
        __syncthreads();
        for (int o = 128; o > 0; o >>= 1) {
            if (t < o) { r1[t] += r1[t + o]; r2[t] += r2[t + o]; }
            __syncthreads();
        }
        if (t == 0) { U[i] = r1[0]; V[i] = r2[0]; }
    } else {
        const int p = blk - 768;
        __shared__ int sb[2];
        if (t < 2) {
            int target = p + t;
            int lo = 0, hi = n;
            while (lo < hi) {
                int mid = (lo + hi) >> 1;
                if (batch[mid] < target) lo = mid + 1; else hi = mid;
            }
            sb[t] = lo;
        }
        __syncthreads();
        const int start = sb[0], end = sb[1];
        float s0 = 0.f, s1 = 0.f, s2 = 0.f, s3 = 0.f;
        int r = start;
        for (; r + 4 <= end; r += 4) {
            s0 += dg[(size_t)(r + 0) * CC + t];
            s1 += dg[(size_t)(r + 1) * CC + t];
            s2 += dg[(size_t)(r + 2) * CC + t];
            s3 += dg[(size_t)(r + 3) * CC + t];
        }
        for (; r < end; r++) s0 += dg[(size_t)r * CC + t];
        float s = (s0 + s1) + (s2 + s3);
        const int cnt = end - start;
        float mv = (cnt > 0) ? s / (float)cnt : 0.f;

        r1[t] = mv; __syncthreads();
        for (int o = 128; o > 0; o >>= 1) { if (t < o) r1[t] += r1[t + o]; __syncthreads(); }
        const float mu = r1[0] * (1.f / CC);
        __syncthreads();
        r1[t] = mv * mv; __syncthreads();
        for (int o = 128; o > 0; o >>= 1) { if (t < o) r1[t] += r1[t + o]; __syncthreads(); }
        const float var = r1[0] * (1.f / CC) - mu * mu;
        const float rstd = rsqrtf(var + 1e-5f);
        G[(size_t)p * CC + t] = (mv - mu) * rstd * dgw[t] + dgb[t];
    }
}

// ---------------- warp-per-row LayerNorm (P rows) ----------------
__global__ void ln_rows(const float* __restrict__ in, const float* __restrict__ w,
                        const float* __restrict__ b, float* __restrict__ out, int rows)
{
    const int warp = blockIdx.x * (blockDim.x >> 5) + (threadIdx.x >> 5);
    if (warp >= rows) return;
    const int lane = threadIdx.x & 31;
    const float* rp = in + (size_t)warp * CC;
    float v[8];
    float s = 0.f, s2 = 0.f;
    #pragma unroll
    for (int i = 0; i < 8; i++) {
        v[i] = rp[lane + 32 * i];
        s  += v[i];
        s2 += v[i] * v[i];
    }
    #pragma unroll
    for (int o = 16; o > 0; o >>= 1) {
        s  += __shfl_xor_sync(0xFFFFFFFFu, s,  o);
        s2 += __shfl_xor_sync(0xFFFFFFFFu, s2, o);
    }
    const float mu  = s * (1.f / CC);
    const float var = s2 * (1.f / CC) - mu * mu;
    const float rstd = rsqrtf(var + 1e-5f);
    float* op = out + (size_t)warp * CC;
    #pragma unroll
    for (int i = 0; i < 8; i++) {
        const int c = lane + 32 * i;
        op[c] = (v[i] - mu) * rstd * w[c] + b[c];
    }
}

// ---------------- small tf32 wmma GEMM: C = A1@B1.T [+ A2@B2.T] + bias, opt relu --------
constexpr int BM = 128, BN = 64, BK = 32;
constexpr int LA = BK + 4;
constexpr int LC = BN + 4;

template<bool RELU, bool CAT>
__global__ __launch_bounds__(256)
void gemm_small(const float* __restrict__ A1, const float* __restrict__ B1, int ldb1,
                const float* __restrict__ A2, const float* __restrict__ B2x, int ldb2,
                float* __restrict__ C, const float* __restrict__ bias)
{
    __shared__ __align__(16) float smem[BM * LC];
    float* As = smem;
    float* Bs = smem + BM * LA;

    const int tid = threadIdx.x;
    const int warpId = tid >> 5;
    const int wm = warpId & 3;
    const int wn = warpId >> 2;
    const size_t gm = (size_t)blockIdx.y * BM;
    const int gn = blockIdx.x * BN;

    wmma::fragment<wmma::accumulator, 16, 16, 8, float> acc[2][2];
    #pragma unroll
    for (int i = 0; i < 2; i++)
        #pragma unroll
        for (int j = 0; j < 2; j++)
            wmma::fill_fragment(acc[i][j], 0.0f);

    const int lr = tid >> 3;
    const int lc = (tid & 7) << 2;
    const int KTOT = CAT ? 2 * CC : CC;

    for (int kt = 0; kt < KTOT; kt += BK) {
        const bool second = CAT && (kt >= CC);
        const float* A = second ? A2 : A1;
        const float* B = second ? B2x : B1;
        const int ldb = second ? ldb2 : ldb1;
        const int k0 = second ? kt - CC : kt;
        __syncthreads();
        #pragma unroll
        for (int p = 0; p < 4; p++) {
            const int r = lr + 32 * p;
            float4 v = *reinterpret_cast<const float4*>(A + (gm + r) * CC + k0 + lc);
            v.x = wmma::__float_to_tf32(v.x); v.y = wmma::__float_to_tf32(v.y);
            v.z = wmma::__float_to_tf32(v.z); v.w = wmma::__float_to_tf32(v.w);
            *reinterpret_cast<float4*>(&As[r * LA + lc]) = v;
        }
        #pragma unroll
        for (int p = 0; p < 2; p++) {
            const int r = lr + 32 * p;
            float4 v = *reinterpret_cast<const float4*>(B + (size_t)(gn + r) * ldb + k0 + lc);
            v.x = wmma::__float_to_tf32(v.x); v.y = wmma::__float_to_tf32(v.y);
            v.z = wmma::__float_to_tf32(v.z); v.w = wmma::__float_to_tf32(v.w);
            *reinterpret_cast<float4*>(&Bs[r * LA + lc]) = v;
        }
        __syncthreads();
        #pragma unroll
        for (int kk = 0; kk < BK; kk += 8) {
            wmma::fragment<wmma::matrix_a, 16, 16, 8, wmma::precision::tf32, wmma::row_major> af[2];
            wmma::fragment<wmma::matrix_b, 16, 16, 8, wmma::precision::tf32, wmma::col_major> bf[2];
            #pragma unroll
            for (int i = 0; i < 2; i++)
                wmma::load_matrix_sync(af[i], &As[(wm * 32 + 16 * i) * LA + kk], LA);
            #pragma unroll
            for (int j = 0; j < 2; j++)
                wmma::load_matrix_sync(bf[j], &Bs[(wn * 32 + 16 * j) * LA + kk], LA);
            #pragma unroll
            for (int i = 0; i < 2; i++)
                #pragma unroll
                for (int j = 0; j < 2; j++)
                    wmma::mma_sync(acc[i][j], af[i], bf[j], acc[i][j]);
        }
    }
    __syncthreads();
    #pragma unroll
    for (int i = 0; i < 2; i++)
        #pragma unroll
        for (int j = 0; j < 2; j++)
            wmma::store_matrix_sync(&smem[(wm * 32 + 16 * i) * LC + wn * 32 + 16 * j],
                                    acc[i][j], LC, wmma::mem_row_major);
    __syncthreads();

    const int ec = tid & 63;
    const int er = tid >> 6;
    #pragma unroll 4
    for (int r = er; r < BM; r += 4) {
        float c = smem[r * LC + ec] + bias[gn + ec];
        if (RELU) c = fmaxf(c, 0.0f);
        C[(gm + r) * CC + gn + ec] = c;
    }
}

// ================= BIG GEMM: fp16 mma.m16n8k16 + ldmatrix =================
// CTA 128x128, BK=32, 8 warps (2 row-blocks of 64 x 4 col-blocks of 32), 2-stage.
// A: fp32 LDG -> in-reg LN stats + fp16 cvt -> STS. B: fp16 via cp.async.
// out[row,col] = relu( rs_r*(orig@W'.T) - rs_r*mu_r*u[col] + v[col] + g2[batch[row],col] )
//               + (orig[row,col]-mu_r)*rs_r*nw[col] + nb[col]
constexpr int QSTAGE = 16384;                  // A 8KB + B 8KB per stage (fp16)
constexpr int EPILD  = 136;
constexpr int SM_MU_OFF = 128 * EPILD * 4;     // 69632
constexpr int SM_RS_OFF = SM_MU_OFF + 512;
constexpr int SM_BIG    = SM_RS_OFF + 512;     // 70656

// 16B-chunk swizzle within a 64B row (conflict-free ldsm over 8 rows)
__device__ __forceinline__ uint32_t hswz(int row, int c16) {
    return (uint32_t)(row * 64 + (c16 ^ ((row >> 1) & 3)) * 16);
}

__global__ __launch_bounds__(256)
void gemm_big_mma(const float* __restrict__ A,      // orig [N,256] raw fp32
                  const __half* __restrict__ Bw,    // W' [256,256] fp16
                  const float* __restrict__ uvec, const float* __restrict__ vvec,
                  const int*   __restrict__ batch, const float* __restrict__ g2,
                  const float* __restrict__ nw, const float* __restrict__ nbv,
                  float* __restrict__ out)
{
    extern __shared__ __align__(1024) char smc[];
    const uint32_t sbm = smem_u32(smc);
    const int tid  = threadIdx.x;
    const int wid  = tid >> 5;
    const int lane = tid & 31;
    const size_t gm = (size_t)blockIdx.y * 128;
    const int gn = blockIdx.x * 128;
    const int wm = wid & 1;        // row block (64 rows)
    const int wn = wid >> 1;       // col block (32 cols)

    float acc[4][4][4];
    #pragma unroll
    for (int i = 0; i < 4; i++)
        #pragma unroll
        for (int j = 0; j < 4; j++)
            #pragma unroll
            for (int e = 0; e < 4; e++) acc[i][j][e] = 0.f;

    // A loader: thread -> row = tid>>1, 16 consecutive floats at half*16
    const int arow = tid >> 1;
    const int ahalf = tid & 1;
    const float* agp = A + (gm + arow) * CC + ahalf * 16;
    float4 r0, r1, r2, r3;               // prefetched A chunk (16 fp32)
    float ss = 0.f, ss2 = 0.f;           // LN stats (exact fp32, in-reg)

    // B loader: thread -> row = tid>>1, two 16B chunks at (tid&1)*2
    const int brow = tid >> 1;
    const int bc0  = (tid & 1) * 2;
    const __half* bgp = Bw + (size_t)(gn + brow) * CC + bc0 * 8;

    // prefetch chunk 0
    r0 = *reinterpret_cast<const float4*>(agp + 0);
    r1 = *reinterpret_cast<const float4*>(agp + 4);
    r2 = *reinterpret_cast<const float4*>(agp + 8);
    r3 = *reinterpret_cast<const float4*>(agp + 12);
    cp_async16(sbm + 8192 + hswz(brow, bc0),     bgp + 0);
    cp_async16(sbm + 8192 + hswz(brow, bc0 + 1), bgp + 8);
    CP_COMMIT();

    // ldsm address components
    const int aR = lane & 15;                       // m within 16
    const int aC = lane >> 4;                       // k 16B-half
    const int bR = ((lane >> 4) << 3) + (lane & 7); // n within 16
    const int bC = (lane >> 3) & 1;                 // k 16B-half

    #pragma unroll 1
    for (int kt = 0; kt < 8; kt++) {
        const uint32_t abase = sbm + (kt & 1) * QSTAGE;
        const uint32_t bbase = abase + 8192;

        // stats + cvt + STS of prefetched A chunk into stage kt
        {
            ss  += (r0.x + r0.y) + (r0.z + r0.w) + (r1.x + r1.y) + (r1.z + r1.w)
                 + (r2.x + r2.y) + (r2.z + r2.w) + (r3.x + r3.y) + (r3.z + r3.w);
            ss2 += r0.x*r0.x + r0.y*r0.y + r0.z*r0.z + r0.w*r0.w
                 + r1.x*r1.x + r1.y*r1.y + r1.z*r1.z + r1.w*r1.w
                 + r2.x*r2.x + r2.y*r2.y + r2.z*r2.z + r2.w*r2.w
                 + r3.x*r3.x + r3.y*r3.y + r3.z*r3.z + r3.w*r3.w;
            uint4 h0, h1;
            h0.x = __half2_raw(__floats2half2_rn(r0.x, r0.y)).x |
                   ((uint32_t)__half2_raw(__floats2half2_rn(r0.x, r0.y)).y << 16);
            // build packed halves explicitly (8 x half2)
            __half2 p0 = __floats2half2_rn(r0.x, r0.y), p1 = __floats2half2_rn(r0.z, r0.w);
            __half2 p2 = __floats2half2_rn(r1.x, r1.y), p3 = __floats2half2_rn(r1.z, r1.w);
            __half2 p4 = __floats2half2_rn(r2.x, r2.y), p5 = __floats2half2_rn(r2.z, r2.w);
            __half2 p6 = __floats2half2_rn(r3.x, r3.y), p7 = __floats2half2_rn(r3.z, r3.w);
            uint4 w0 = make_uint4(*(uint32_t*)&p0, *(uint32_t*)&p1, *(uint32_t*)&p2, *(uint32_t*)&p3);
            uint4 w1 = make_uint4(*(uint32_t*)&p4, *(uint32_t*)&p5, *(uint32_t*)&p6, *(uint32_t*)&p7);
            *reinterpret_cast<uint4*>(smc + (abase - sbm) + hswz(arow, ahalf * 2))     = w0;
            *reinterpret_cast<uint4*>(smc + (abase - sbm) + hswz(arow, ahalf * 2 + 1)) = w1;
        }
        CP_WAIT(0);
        __syncthreads();            // stage kt fully resident (A via STS, B via cp.async)

        // prefetch chunk kt+1 (overlaps math below)
        if (kt < 7) {
            const float* ag = agp + (kt + 1) * 32;
            r0 = *reinterpret_cast<const float4*>(ag + 0);
            r1 = *reinterpret_cast<const float4*>(ag + 4);
            r2 = *reinterpret_cast<const float4*>(ag + 8);
            r3 = *reinterpret_cast<const float4*>(ag + 12);
            const uint32_t nb2 = sbm + ((kt + 1) & 1) * QSTAGE + 8192;
            cp_async16(nb2 + hswz(brow, bc0),     bgp + (kt + 1) * 32);
            cp_async16(nb2 + hswz(brow, bc0 + 1), bgp + (kt + 1) * 32 + 8);
            CP_COMMIT();
        }

        // math on stage kt: 2 k16-steps
        #pragma unroll
        for (int kk = 0; kk < 2; kk++) {
            uint32_t bv[2][4];
            #pragma unroll
            for (int nb = 0; nb < 2; nb++) {
                const int n = wn * 32 + nb * 16 + bR;
                ldsm4(bv[nb][0], bv[nb][1], bv[nb][2], bv[nb][3],
                      bbase + hswz(n, kk * 2 + bC));
            }
            #pragma unroll
            for (int mi = 0; mi < 4; mi++) {
                uint32_t av[4];
                const int m = wm * 64 + mi * 16 + aR;
                ldsm4(av[0], av[1], av[2], av[3], abase + hswz(m, kk * 2 + aC));
                #pragma unroll
                for (int nb = 0; nb < 2; nb++) {
                    mma_f16(acc[mi][nb * 2 + 0], av[0], av[1], av[2], av[3],
                            bv[nb][0], bv[nb][1]);
                    mma_f16(acc[mi][nb * 2 + 1], av[0], av[1], av[2], av[3],
                            bv[nb][2], bv[nb][3]);
                }
            }
        }
    }

    // finalize LN stats (partner thread tid^1 is in the same warp, same row)
    ss  += __shfl_xor_sync(0xFFFFFFFFu, ss,  1);
    ss2 += __shfl_xor_sync(0xFFFFFFFFu, ss2, 1);
    if (ahalf == 0) {
        const float m = ss * (1.f / CC);
        *reinterpret_cast<float*>(smc + SM_MU_OFF + arow * 4) = m;
        *reinterpret_cast<float*>(smc + SM_RS_OFF + arow * 4) =
            rsqrtf(ss2 * (1.f / CC) - m * m + 1e-5f);
    }
    __syncthreads();   // all math done before epilogue overwrites stage smem

    // acc -> epilogue smem
    {
        float* ep = reinterpret_cast<float*>(smc);
        const int er0 = lane >> 2;
        const int ec0 = (lane & 3) * 2;
        #pragma unroll
        for (int mi = 0; mi < 4; mi++) {
            const int rb = wm * 64 + mi * 16 + er0;
            #pragma unroll
            for (int ni = 0; ni < 4; ni++) {
                const int cb = wn * 32 + ni * 8 + ec0;
                *reinterpret_cast<float2*>(ep + rb * EPILD + cb) =
                    make_float2(acc[mi][ni][0], acc[mi][ni][1]);
                *reinterpret_cast<float2*>(ep + (rb + 8) * EPILD + cb) =
                    make_float2(acc[mi][ni][2], acc[mi][ni][3]);
            }
        }
    }
    __syncthreads();

    // fused epilogue
    {
        const float* ep  = reinterpret_cast<const float*>(smc);
        const float* smu = reinterpret_cast<const float*>(smc + SM_MU_OFF);
        const float* srs = reinterpret_cast<const float*>(smc + SM_RS_OFF);
        const int ec = tid & 127;
        const int col = gn + ec;
        const float un = uvec[col], vn = vvec[col];
        const float w_ = nw[col],  b_ = nbv[col];
        #pragma unroll 4
        for (int r = tid >> 7; r < 128; r += 2) {
            const size_t row = gm + r;
            const float m = smu[r], rs = srs[r];
            float c = ep[r * EPILD + ec] * rs - m * rs * un + vn
                    + g2[(size_t)batch[row] * CC + col];
            c = fmaxf(c, 0.0f);
            const float o = A[row * CC + col];   // L2-hot reload
            out[row * CC + col] = c + (o - m) * rs * w_ + b_;
        }
    }
}

// ---------------- launcher ----------------
extern "C" void kernel_launch(void* const* d_in, const int* in_sizes, int n_in,
                              void* d_out, int out_size)
{
    const float* orig       = (const float*)d_in[0];
    const float* dgf        = (const float*)d_in[1];
    const float* node_w     = (const float*)d_in[2];
    const float* node_b     = (const float*)d_in[3];
    const float* dg_w       = (const float*)d_in[4];
    const float* dg_b       = (const float*)d_in[5];
    const float* in_proj_w  = (const float*)d_in[6];
    const float* in_proj_b  = (const float*)d_in[7];
    const float* out_proj_w = (const float*)d_in[8];
    const float* out_proj_b = (const float*)d_in[9];
    const float* ffn_w      = (const float*)d_in[10];
    const float* ffn_b      = (const float*)d_in[11];
    const float* l1w        = (const float*)d_in[12];
    const float* l1b        = (const float*)d_in[13];
    const float* l2w        = (const float*)d_in[14];
    const float* l2b        = (const float*)d_in[15];
    const float* fuse_w     = (const float*)d_in[16];
    const float* fuse_b     = (const float*)d_in[17];
    const int*   batch      = (const int*)d_in[18];
    const int n = in_sizes[0] / CC;   // 262144

    float *G, *ATT, *Y, *H, *G2, *WVO, *BVO, *M1, *B2, *U, *V;
    __half *WFh;
    cudaGetSymbolAddress((void**)&G,   g_G);
    cudaGetSymbolAddress((void**)&ATT, g_ATT);
    cudaGetSymbolAddress((void**)&Y,   g_Y);
    cudaGetSymbolAddress((void**)&H,   g_H);
    cudaGetSymbolAddress((void**)&G2,  g_G2);
    cudaGetSymbolAddress((void**)&WVO, g_WVO);
    cudaGetSymbolAddress((void**)&BVO, g_BVO);
    cudaGetSymbolAddress((void**)&M1,  g_M1);
    cudaGetSymbolAddress((void**)&B2,  g_B2);
    cudaGetSymbolAddress((void**)&WFh, g_WFh);
    cudaGetSymbolAddress((void**)&U,   g_U);
    cudaGetSymbolAddress((void**)&V,   g_V);

    cudaFuncSetAttribute(gemm_big_mma, cudaFuncAttributeMaxDynamicSharedMemorySize, SM_BIG);

    const dim3 sg(CC / BN, PP / BM);   // (4, 32)

    // 0: all precomputes + segment-mean/LN
    fused_pre_seg<<<768 + PP, 256>>>(
        out_proj_w, in_proj_w, in_proj_b, out_proj_b,
        fuse_w, l2w, l2b, fuse_b, node_w, node_b,
        dgf, batch, n, dg_w, dg_b,
        WVO, BVO, M1, B2, WFh, U, V, G);
    // 1: ATT = G @ WVO.T + BVO
    gemm_small<false, false><<<sg, 256>>>(G, WVO, CC, nullptr, nullptr, 0, ATT, BVO);
    // 2: Y = LN(ATT)
    ln_rows<<<PP / 8, 256>>>(ATT, ffn_w, ffn_b, Y, PP);
    // 3: H = relu(Y @ l1w.T + l1b)
    gemm_small<true, false><<<sg, 256>>>(Y, l1w, CC, nullptr, nullptr, 0, H, l1b);
    // 4: G2 = H @ M1.T + ATT @ Wf2.T + B2
    gemm_small<false, true><<<sg, 256>>>(H, M1, CC, ATT, fuse_w + CC, 2 * CC, G2, B2);
    // 5: big fused node GEMM (fp16 tensor path)
    gemm_big_mma<<<dim3(2, n / 128), 256, SM_BIG>>>(
        orig, WFh, U, V, batch, G2, node_w, node_b, (float*)d_out);
}